// round 13
// baseline (speedup 1.0000x reference)
#include <cuda_runtime.h>

#define BB 8
#define NN 4096
#define DD 64
#define KK 16
#define LL 4
#define PREDN 64
#define BN (BB*NN)

typedef unsigned long long ull;

// ---- packed f32x2 helpers (sm_100a) ----
__device__ __forceinline__ void ffma2(ull& acc, ull a, ull b) {
    asm("fma.rn.f32x2 %0, %1, %2, %0;" : "+l"(acc) : "l"(a), "l"(b));
}
__device__ __forceinline__ void fadd2(ull& a, ull b) {
    asm("add.rn.f32x2 %0, %0, %1;" : "+l"(a) : "l"(b));
}
__device__ __forceinline__ ull pack2(float lo, float hi) {
    ull r; asm("mov.b64 %0, {%1, %2};" : "=l"(r) : "f"(lo), "f"(hi)); return r;
}
__device__ __forceinline__ void unpack2(float& lo, float& hi, ull v) {
    asm("mov.b64 {%0, %1}, %2;" : "=f"(lo), "=f"(hi) : "l"(v));
}

// ---------------- scratch (static device globals; no allocation) ----------------
__device__ float g_xcur[BN*DD];                 // current features
__device__ float g_xcat[BN*(LL+1)*DD];          // concat buffer [p][320]
__device__ float g_norm[BN];                    // |x|^2
__device__ float g_norm3[BN];                   // |c|^2
__device__ int   g_idxd[BN*KK];                 // coords knn (GLOBAL point indices)
__device__ int   g_idxf[BN*KK];                 // feature knn (GLOBAL point indices)
__device__ float g_Af[BN*DD], g_Bf[BN*DD], g_Ad[BN*DD], g_Bd[BN*DD];
__device__ float g_Of[BN*DD], g_Od[BN*DD];
__device__ float g_Cf1[LL*DD*DD], g_Cd1[LL*DD*DD];  // per-layer W1_top - W1_bot combos
__device__ float g_site[BN*PREDN];
__device__ float g_pool[BB*PREDN];

// ---------------- init: xcur = feats, xcat[:,0:64] = feats, norm ----------------
__global__ void k_init(const float* __restrict__ feats) {
    int t = blockIdx.x * 256 + threadIdx.x;     // float2 index, total BN*32
    float2 v = ((const float2*)feats)[t];
    ((float2*)g_xcur)[t] = v;
    int p = t >> 5, pr = t & 31;
    ((float2*)(g_xcat + p*320))[pr] = v;
    float s = v.x*v.x + v.y*v.y;
    #pragma unroll
    for (int o = 16; o; o >>= 1) s += __shfl_down_sync(0xffffffffu, s, o);
    if ((threadIdx.x & 31) == 0) g_norm[p] = s;
}

__global__ void k_norm3(const float* __restrict__ coords) {
    int p = blockIdx.x * 256 + threadIdx.x;
    if (p < BN) {
        float a = coords[p*3], b = coords[p*3+1], c = coords[p*3+2];
        g_norm3[p] = a*a + b*b + c*c;
    }
}

// ---------------- KNN on coords (D=3) ----------------
__global__ void k_knn3(const float* __restrict__ coords) {
    int b = blockIdx.y;
    int tid = threadIdx.x;                      // 128
    int q = blockIdx.x * 128 + tid;
    int gq = b*NN + q;
    float q0 = coords[gq*3+0], q1 = coords[gq*3+1], q2 = coords[gq*3+2];
    float qn = g_norm3[gq];
    float hd[KK]; int hi[KK];
    #pragma unroll
    for (int s = 0; s < KK; ++s) { hd[s] = 1e30f; hi[s] = 0; }

    __shared__ float s0[128], s1[128], s2[128], sn[128];
    for (int jt = 0; jt < NN; jt += 128) {
        int gj = b*NN + jt + tid;
        s0[tid] = coords[gj*3+0];
        s1[tid] = coords[gj*3+1];
        s2[tid] = coords[gj*3+2];
        sn[tid] = g_norm3[gj];
        __syncthreads();
        #pragma unroll 4
        for (int jj = 0; jj < 128; ++jj) {
            float d2 = qn + sn[jj] - 2.f*(q0*s0[jj] + q1*s1[jj] + q2*s2[jj]);
            int j = jt + jj;
            if (j != q && d2 < hd[KK-1]) {
                float cd = d2; int ci = j;
                #pragma unroll
                for (int s = 0; s < KK; ++s) {
                    if (cd < hd[s]) {
                        float td = hd[s]; int ti = hi[s];
                        hd[s] = cd; hi[s] = ci; cd = td; ci = ti;
                    }
                }
            }
        }
        __syncthreads();
    }
    #pragma unroll
    for (int s = 0; s < KK; ++s) g_idxd[gq*KK + s] = b*NN + hi[s];   // GLOBAL index
}

// ---------------- combos for ALL layers, once ----------------
__global__ void k_combo_all(const float* __restrict__ Wf1, const float* __restrict__ Wd1) {
    int i = blockIdx.x * 256 + threadIdx.x;     // 0..16383
    if (i < LL*4096) {
        int li = i >> 12, idx = i & 4095;
        const float* f = Wf1 + li*128*64;
        g_Cf1[i] = f[idx] - f[4096 + idx];
        const float* d = Wd1 + li*134*64;
        g_Cd1[i] = d[idx] - d[4096 + idx];
    }
}

// ==== fused kernel: blocks 0..255 = feature-KNN, blocks 256..1279 = per-point pre ====
__global__ void __launch_bounds__(128) k_ap(const float* __restrict__ coords,
                                            const float* __restrict__ Wf1,
                                            const float* __restrict__ Wd1,
                                            const float* __restrict__ bf1,
                                            const float* __restrict__ bd1, int li) {
    int bid = blockIdx.x;
    int tid = threadIdx.x;            // 128

    if (bid < 256) {
        // ---------------- knn64 role (one thread per query, 2-wide candidates) --------
        int gq = bid * 128 + tid;
        int b = gq >> 12;

        ulonglong2 qr[16];
        const ulonglong2* qp = (const ulonglong2*)(g_xcur + gq*64);
        #pragma unroll
        for (int i = 0; i < 16; ++i) qr[i] = qp[i];
        float qn = g_norm[gq];
        int q = gq & (NN - 1);

        float hd[KK]; int hi[KK];
        #pragma unroll
        for (int s = 0; s < KK; ++s) { hd[s] = 1e30f; hi[s] = 0; }

        __shared__ ulonglong2 sdb[64*16];
        __shared__ float      sn[64];

        for (int jt = 0; jt < NN; jt += 64) {
            const ulonglong2* src = (const ulonglong2*)(g_xcur + (b*NN + jt)*64);
            #pragma unroll
            for (int u = 0; u < 8; ++u) sdb[tid + u*128] = src[tid + u*128];
            if (tid < 64) sn[tid] = g_norm[b*NN + jt + tid];
            __syncthreads();

            for (int jj = 0; jj < 64; jj += 2) {
                const ulonglong2* pa = sdb + jj*16;
                const ulonglong2* pb = pa + 16;
                ull a0=0ull,a1=0ull,a2=0ull,a3=0ull;
                ull c0=0ull,c1=0ull,c2=0ull,c3=0ull;
                #pragma unroll
                for (int i = 0; i < 16; i += 2) {
                    ulonglong2 va0 = pa[i], va1 = pa[i+1];
                    ulonglong2 vb0 = pb[i], vb1 = pb[i+1];
                    ffma2(a0, va0.x, qr[i].x);   ffma2(a1, va0.y, qr[i].y);
                    ffma2(a2, va1.x, qr[i+1].x); ffma2(a3, va1.y, qr[i+1].y);
                    ffma2(c0, vb0.x, qr[i].x);   ffma2(c1, vb0.y, qr[i].y);
                    ffma2(c2, vb1.x, qr[i+1].x); ffma2(c3, vb1.y, qr[i+1].y);
                }
                fadd2(a0, a1); fadd2(a2, a3); fadd2(a0, a2);
                fadd2(c0, c1); fadd2(c2, c3); fadd2(c0, c2);
                float la, ha, lc, hc;
                unpack2(la, ha, a0);
                unpack2(lc, hc, c0);
                float dA = qn + sn[jj]   - 2.f*(la + ha);
                float dB = qn + sn[jj+1] - 2.f*(lc + hc);

                int ja = jt + jj;
                if (ja != q && dA < hd[KK-1]) {
                    float cd = dA; int ci = ja;
                    #pragma unroll
                    for (int s = 0; s < KK; ++s) {
                        if (cd < hd[s]) {
                            float td = hd[s]; int ti = hi[s];
                            hd[s] = cd; hi[s] = ci; cd = td; ci = ti;
                        }
                    }
                }
                int jb = jt + jj + 1;
                if (jb != q && dB < hd[KK-1]) {
                    float cd = dB; int ci = jb;
                    #pragma unroll
                    for (int s = 0; s < KK; ++s) {
                        if (cd < hd[s]) {
                            float td = hd[s]; int ti = hi[s];
                            hd[s] = cd; hi[s] = ci; cd = td; ci = ti;
                        }
                    }
                }
            }
            __syncthreads();
        }
        #pragma unroll
        for (int s = 0; s < KK; ++s) g_idxf[gq*KK + s] = b*NN + hi[s];
    } else {
        // ---------------- pre role: 32 points, two column-halves ----------------
        int p0 = (bid - 256) * 32;
        __shared__ float sX[32*65];
        __shared__ float sC[32*4];
        {
            int base = p0 * 64;
            #pragma unroll
            for (int u = 0; u < 16; ++u) {
                int f = tid + u*128;
                sX[(f >> 6)*65 + (f & 63)] = g_xcur[base + f];
            }
            if (tid < 96) { int pp = tid / 3, e = tid % 3; sC[pp*4 + e] = coords[(p0+pp)*3 + e]; }
        }
        __syncthreads();

        int l = tid & 31;
        int p = p0 + l;

        const float* Cf  = g_Cf1 + li*4096;
        const float* Cd  = g_Cd1 + li*4096;
        const float* Wfb = Wf1 + li*128*64 + 64*64;
        const float* Wdb = Wd1 + li*134*64 + 64*64;
        const float* Wdc = Wd1 + li*134*64 + 128*64;
        const float* Wdn = Wd1 + li*134*64 + 131*64;

        #pragma unroll
        for (int half = 0; half < 2; ++half) {
            int c0 = (tid >> 5) * 8 + half * 32;

            ull afp[4] = {0,0,0,0}, bfp[4] = {0,0,0,0};
            ull adp[4] = {0,0,0,0}, bdp[4] = {0,0,0,0};

            #pragma unroll 4
            for (int d = 0; d < 64; ++d) {
                float xv = sX[l*65 + d];
                ull xx = pack2(xv, xv);
                ulonglong2 a0 = __ldg((const ulonglong2*)(Cf + d*64 + c0));
                ulonglong2 a1 = __ldg((const ulonglong2*)(Cf + d*64 + c0 + 4));
                ulonglong2 b0 = __ldg((const ulonglong2*)(Wfb + d*64 + c0));
                ulonglong2 b1 = __ldg((const ulonglong2*)(Wfb + d*64 + c0 + 4));
                ulonglong2 e0 = __ldg((const ulonglong2*)(Cd + d*64 + c0));
                ulonglong2 e1 = __ldg((const ulonglong2*)(Cd + d*64 + c0 + 4));
                ulonglong2 f0 = __ldg((const ulonglong2*)(Wdb + d*64 + c0));
                ulonglong2 f1 = __ldg((const ulonglong2*)(Wdb + d*64 + c0 + 4));
                ffma2(afp[0], a0.x, xx); ffma2(afp[1], a0.y, xx);
                ffma2(afp[2], a1.x, xx); ffma2(afp[3], a1.y, xx);
                ffma2(bfp[0], b0.x, xx); ffma2(bfp[1], b0.y, xx);
                ffma2(bfp[2], b1.x, xx); ffma2(bfp[3], b1.y, xx);
                ffma2(adp[0], e0.x, xx); ffma2(adp[1], e0.y, xx);
                ffma2(adp[2], e1.x, xx); ffma2(adp[3], e1.y, xx);
                ffma2(bdp[0], f0.x, xx); ffma2(bdp[1], f0.y, xx);
                ffma2(bdp[2], f1.x, xx); ffma2(bdp[3], f1.y, xx);
            }
            #pragma unroll
            for (int e = 0; e < 3; ++e) {
                float cv = sC[l*4 + e];
                ull cc = pack2(cv, cv);
                ulonglong2 u0 = __ldg((const ulonglong2*)(Wdc + e*64 + c0));
                ulonglong2 u1 = __ldg((const ulonglong2*)(Wdc + e*64 + c0 + 4));
                ulonglong2 v0 = __ldg((const ulonglong2*)(Wdn + e*64 + c0));
                ulonglong2 v1 = __ldg((const ulonglong2*)(Wdn + e*64 + c0 + 4));
                ffma2(adp[0], u0.x, cc); ffma2(adp[1], u0.y, cc);
                ffma2(adp[2], u1.x, cc); ffma2(adp[3], u1.y, cc);
                ffma2(bdp[0], v0.x, cc); ffma2(bdp[1], v0.y, cc);
                ffma2(bdp[2], v1.x, cc); ffma2(bdp[3], v1.y, cc);
            }

            float af[8], bfv[8], ad[8], bdv[8];
            #pragma unroll
            for (int j = 0; j < 4; ++j) {
                unpack2(af[2*j],  af[2*j+1],  afp[j]);
                unpack2(bfv[2*j], bfv[2*j+1], bfp[j]);
                unpack2(ad[2*j],  ad[2*j+1],  adp[j]);
                unpack2(bdv[2*j], bdv[2*j+1], bdp[j]);
            }
            #pragma unroll
            for (int j = 0; j < 8; ++j) {
                af[j] += bf1[li*64 + c0 + j];
                ad[j] += bd1[li*64 + c0 + j];
            }
            int o = p*64 + c0;
            #pragma unroll
            for (int j = 0; j < 8; ++j) {
                g_Af[o+j] = af[j]; g_Bf[o+j] = bfv[j];
                g_Ad[o+j] = ad[j]; g_Bd[o+j] = bdv[j];
            }
        }
    }
}

// ---- fused edge kernel, both branches: blocks 0..1023 = f, 1024..2047 = d ----
__global__ void k_edge2(const float* __restrict__ Wf2g, const float* __restrict__ bf2,
                        const float* __restrict__ Wd2g, const float* __restrict__ bd2, int li) {
    int bid = blockIdx.x;
    int branch = bid >> 10;
    int p0 = (bid & 1023) * 32;

    const float* A    = branch ? g_Ad : g_Af;
    const float* Bm   = branch ? g_Bd : g_Bf;
    const int*   idx  = branch ? g_idxd : g_idxf;
    float*       Out  = branch ? g_Od : g_Of;
    const float* W    = (branch ? Wd2g : Wf2g) + li*64*64;
    const float* bias = (branch ? bd2 : bf2) + li*64;

    __shared__ float sA[32*65];
    __shared__ float sH[2][32*65];
    __shared__ __align__(16) float sW[64*64];
    __shared__ int sI[32*KK];

    int tid = threadIdx.x;            // 256

    #pragma unroll
    for (int u = 0; u < 16; ++u) sW[tid + u*256] = __ldg(W + tid + u*256);
    #pragma unroll
    for (int u = 0; u < 8; ++u) {
        int f = tid + u*256;
        sA[(f >> 6)*65 + (f & 63)] = A[p0*64 + f];
    }
    sI[tid]       = idx[p0*KK + tid];
    sI[tid + 256] = idx[p0*KK + tid + 256];
    __syncthreads();

    int w = tid >> 5, l = tid & 31;
    int c0 = w * 8;
    int pt = tid >> 3;
    int dd0 = (tid & 7) * 8;

    const ulonglong2* sW2 = (const ulonglong2*)sW;

    float4 v0, v1;
    {
        int j = sI[pt*KK];
        const float4* Brow = (const float4*)(Bm + j*64 + dd0);
        v0 = __ldg(Brow); v1 = __ldg(Brow + 1);
    }

    float best[8];
    #pragma unroll
    for (int j = 0; j < 8; ++j) best[j] = -1e30f;

    for (int k = 0; k < KK; ++k) {
        int buf = k & 1;
        float hb[8] = {v0.x, v0.y, v0.z, v0.w, v1.x, v1.y, v1.z, v1.w};
        #pragma unroll
        for (int u = 0; u < 8; ++u) {
            float h = sA[pt*65 + dd0 + u] + hb[u];
            sH[buf][pt*65 + dd0 + u] = h > 0.f ? h : 0.01f*h;
        }
        __syncthreads();

        if (k + 1 < KK) {
            int j = sI[pt*KK + k + 1];
            const float4* Brow = (const float4*)(Bm + j*64 + dd0);
            v0 = __ldg(Brow); v1 = __ldg(Brow + 1);
        }

        ull a0 = 0ull, a1 = 0ull, a2 = 0ull, a3 = 0ull;
        #pragma unroll
        for (int d = 0; d < 64; ++d) {
            float hv = sH[buf][l*65 + d];
            ull hh = pack2(hv, hv);
            ulonglong2 wa = sW2[d*16 + w*2];
            ulonglong2 wb = sW2[d*16 + w*2 + 1];
            ffma2(a0, wa.x, hh);
            ffma2(a1, wa.y, hh);
            ffma2(a2, wb.x, hh);
            ffma2(a3, wb.y, hh);
        }
        float t0,t1;
        unpack2(t0,t1,a0); best[0] = fmaxf(best[0], t0); best[1] = fmaxf(best[1], t1);
        unpack2(t0,t1,a1); best[2] = fmaxf(best[2], t0); best[3] = fmaxf(best[3], t1);
        unpack2(t0,t1,a2); best[4] = fmaxf(best[4], t0); best[5] = fmaxf(best[5], t1);
        unpack2(t0,t1,a3); best[6] = fmaxf(best[6], t0); best[7] = fmaxf(best[7], t1);
    }

    int p = p0 + l;
    #pragma unroll
    for (int j = 0; j < 8; ++j) Out[p*64 + c0 + j] = best[j] + bias[c0 + j];
}

// ---------------- combine branches, update xcur + xcat + norm ----------------
__global__ void k_combine(int li) {
    int t = blockIdx.x * 256 + threadIdx.x;     // float2 index, total BN*32
    float2 a = ((const float2*)g_Of)[t];
    float2 c = ((const float2*)g_Od)[t];
    float2 v; v.x = a.x + c.x; v.y = a.y + c.y;
    ((float2*)g_xcur)[t] = v;
    int p = t >> 5, pr = t & 31;
    ((float2*)(g_xcat + p*320))[pr + (li+1)*32] = v;
    float s = v.x*v.x + v.y*v.y;
    #pragma unroll
    for (int o = 16; o; o >>= 1) s += __shfl_down_sync(0xffffffffu, s, o);
    if ((threadIdx.x & 31) == 0) g_norm[p] = s;
}

// ---------------- site MLP: xcat[320] @ Ws[320,64] + bs (f32x2) ----------------
__global__ void k_site(const float* __restrict__ Ws, const float* __restrict__ bs) {
    __shared__ float sX[32*321];
    int tid = threadIdx.x;            // 256
    int p0 = blockIdx.x * 32;
    for (int u = 0; u < 40; ++u) {
        int f = tid + u*256;          // 0..10239
        sX[(f / 320)*321 + (f % 320)] = g_xcat[p0*320 + f];
    }
    __syncthreads();

    int w = tid >> 5, l = tid & 31;
    int c0 = w * 8;
    ull a0 = 0ull, a1 = 0ull, a2 = 0ull, a3 = 0ull;
    #pragma unroll 8
    for (int d = 0; d < 320; ++d) {
        float xv = sX[l*321 + d];
        ull xx = pack2(xv, xv);
        ulonglong2 w0 = __ldg((const ulonglong2*)(Ws + d*64 + c0));
        ulonglong2 w1 = __ldg((const ulonglong2*)(Ws + d*64 + c0 + 4));
        ffma2(a0, w0.x, xx);
        ffma2(a1, w0.y, xx);
        ffma2(a2, w1.x, xx);
        ffma2(a3, w1.y, xx);
    }
    float acc[8];
    unpack2(acc[0], acc[1], a0);
    unpack2(acc[2], acc[3], a1);
    unpack2(acc[4], acc[5], a2);
    unpack2(acc[6], acc[7], a3);
    int p = p0 + l;
    #pragma unroll
    for (int j = 0; j < 8; ++j) g_site[p*64 + c0 + j] = acc[j] + bs[c0 + j];
}

// ---------------- max pool over N ----------------
__global__ void k_pool() {
    int b = blockIdx.x;
    int tid = threadIdx.x;            // 256
    int c = tid & 63, g = tid >> 6;
    float m = -1e30f;
    for (int n = g; n < NN; n += 4) m = fmaxf(m, g_site[(b*NN + n)*64 + c]);
    __shared__ float red[256];
    red[tid] = m;
    __syncthreads();
    if (tid < 128) red[tid] = fmaxf(red[tid], red[tid + 128]);
    __syncthreads();
    if (tid < 64) g_pool[b*64 + tid] = fmaxf(red[tid], red[tid + 64]);
}

// ---------------- head ----------------
__global__ void k_head(const float* __restrict__ Wc1, const float* __restrict__ bc1,
                       const float* __restrict__ Wc2, const float* __restrict__ bc2,
                       float* __restrict__ out) {
    __shared__ float sp[BB*64], sh[BB*64];
    int tid = threadIdx.x;            // 512
    sp[tid] = g_pool[tid];
    __syncthreads();
    {
        int b = tid >> 6, c = tid & 63;
        float a = 0.f;
        #pragma unroll 8
        for (int d = 0; d < 64; ++d) a += sp[b*64 + d] * __ldg(Wc1 + d*64 + c);
        a += bc1[c];
        sh[tid] = a > 0.f ? a : 0.01f*a;
    }
    __syncthreads();
    if (tid < BB*3) {
        int b = tid / 3, e = tid % 3;
        float a = 0.f;
        #pragma unroll 8
        for (int c = 0; c < 64; ++c) a += sh[b*64 + c] * __ldg(Wc2 + c*3 + e);
        out[tid] = a + bc2[e];
    }
}

// ---------------- launcher ----------------
extern "C" void kernel_launch(void* const* d_in, const int* in_sizes, int n_in,
                              void* d_out, int out_size) {
    const float* feats  = (const float*)d_in[0];
    const float* coords = (const float*)d_in[1];
    const float* Wd1 = (const float*)d_in[2];
    const float* bd1 = (const float*)d_in[3];
    const float* Wd2 = (const float*)d_in[4];
    const float* bd2 = (const float*)d_in[5];
    const float* Wf1 = (const float*)d_in[6];
    const float* bf1 = (const float*)d_in[7];
    const float* Wf2 = (const float*)d_in[8];
    const float* bf2 = (const float*)d_in[9];
    const float* Ws  = (const float*)d_in[10];
    const float* bs  = (const float*)d_in[11];
    const float* Wc1 = (const float*)d_in[12];
    const float* bc1 = (const float*)d_in[13];
    const float* Wc2 = (const float*)d_in[14];
    const float* bc2 = (const float*)d_in[15];

    k_init<<<BN*32/256, 256>>>(feats);          // also writes g_norm for layer 0
    k_norm3<<<(BN + 255)/256, 256>>>(coords);
    {
        dim3 g(NN/128, BB);
        k_knn3<<<g, 128>>>(coords);
    }
    k_combo_all<<<(LL*4096 + 255)/256, 256>>>(Wf1, Wd1);
    for (int li = 0; li < LL; ++li) {
        k_ap<<<256 + BN/32, 128>>>(coords, Wf1, Wd1, bf1, bd1, li);
        k_edge2<<<2*BN/32, 256>>>(Wf2, bf2, Wd2, bd2, li);
        k_combine<<<BN*32/256, 256>>>(li);      // also writes g_norm for next layer
    }
    k_site<<<BN/32, 256>>>(Ws, bs);
    k_pool<<<BB, 256>>>();
    k_head<<<1, 512>>>(Wc1, bc1, Wc2, bc2, (float*)d_out);
}

// round 14
// speedup vs baseline: 1.1428x; 1.1428x over previous
#include <cuda_runtime.h>

#define BB 8
#define NN 4096
#define DD 64
#define KK 16
#define LL 4
#define PREDN 64
#define BN (BB*NN)

typedef unsigned long long ull;

// ---- packed f32x2 helpers (sm_100a) ----
__device__ __forceinline__ void ffma2(ull& acc, ull a, ull b) {
    asm("fma.rn.f32x2 %0, %1, %2, %0;" : "+l"(acc) : "l"(a), "l"(b));
}
__device__ __forceinline__ void fadd2(ull& a, ull b) {
    asm("add.rn.f32x2 %0, %0, %1;" : "+l"(a) : "l"(b));
}
__device__ __forceinline__ ull pack2(float lo, float hi) {
    ull r; asm("mov.b64 %0, {%1, %2};" : "=l"(r) : "f"(lo), "f"(hi)); return r;
}
__device__ __forceinline__ void unpack2(float& lo, float& hi, ull v) {
    asm("mov.b64 {%0, %1}, %2;" : "=f"(lo), "=f"(hi) : "l"(v));
}

// ---------------- scratch (static device globals; no allocation) ----------------
__device__ float g_xcur[BN*DD];                 // current features
__device__ float g_xcat[BN*(LL+1)*DD];          // concat buffer [p][320]
__device__ float g_norm[BN];                    // |x|^2
__device__ float g_norm3[BN];                   // |c|^2
__device__ int   g_idxd[BN*KK];                 // coords knn (GLOBAL point indices)
__device__ int   g_idxf[BN*KK];                 // feature knn (GLOBAL point indices)
__device__ float g_Af[BN*DD], g_Bf[BN*DD], g_Ad[BN*DD], g_Bd[BN*DD];
__device__ float g_Of[BN*DD], g_Od[BN*DD];
__device__ float g_Cf1[LL*DD*DD], g_Cd1[LL*DD*DD];  // per-layer W1_top - W1_bot combos
__device__ float g_site[BN*PREDN];
__device__ float g_pool[BB*PREDN];

// ---------------- init: xcur = feats, xcat[:,0:64] = feats, norm ----------------
__global__ void k_init(const float* __restrict__ feats) {
    int t = blockIdx.x * 256 + threadIdx.x;     // float2 index, total BN*32
    float2 v = ((const float2*)feats)[t];
    ((float2*)g_xcur)[t] = v;
    int p = t >> 5, pr = t & 31;
    ((float2*)(g_xcat + p*320))[pr] = v;
    float s = v.x*v.x + v.y*v.y;
    #pragma unroll
    for (int o = 16; o; o >>= 1) s += __shfl_down_sync(0xffffffffu, s, o);
    if ((threadIdx.x & 31) == 0) g_norm[p] = s;
}

__global__ void k_norm3(const float* __restrict__ coords) {
    int p = blockIdx.x * 256 + threadIdx.x;
    if (p < BN) {
        float a = coords[p*3], b = coords[p*3+1], c = coords[p*3+2];
        g_norm3[p] = a*a + b*b + c*c;
    }
}

// ---------------- KNN on coords (D=3) ----------------
__global__ void k_knn3(const float* __restrict__ coords) {
    int b = blockIdx.y;
    int tid = threadIdx.x;                      // 128
    int q = blockIdx.x * 128 + tid;
    int gq = b*NN + q;
    float q0 = coords[gq*3+0], q1 = coords[gq*3+1], q2 = coords[gq*3+2];
    float qn = g_norm3[gq];
    float hd[KK]; int hi[KK];
    #pragma unroll
    for (int s = 0; s < KK; ++s) { hd[s] = 1e30f; hi[s] = 0; }

    __shared__ float s0[128], s1[128], s2[128], sn[128];
    for (int jt = 0; jt < NN; jt += 128) {
        int gj = b*NN + jt + tid;
        s0[tid] = coords[gj*3+0];
        s1[tid] = coords[gj*3+1];
        s2[tid] = coords[gj*3+2];
        sn[tid] = g_norm3[gj];
        __syncthreads();
        #pragma unroll 4
        for (int jj = 0; jj < 128; ++jj) {
            float d2 = qn + sn[jj] - 2.f*(q0*s0[jj] + q1*s1[jj] + q2*s2[jj]);
            int j = jt + jj;
            if (j != q && d2 < hd[KK-1]) {
                float cd = d2; int ci = j;
                #pragma unroll
                for (int s = 0; s < KK; ++s) {
                    if (cd < hd[s]) {
                        float td = hd[s]; int ti = hi[s];
                        hd[s] = cd; hi[s] = ci; cd = td; ci = ti;
                    }
                }
            }
        }
        __syncthreads();
    }
    #pragma unroll
    for (int s = 0; s < KK; ++s) g_idxd[gq*KK + s] = b*NN + hi[s];   // GLOBAL index
}

// ---- KNN on features (D=64): single pass, 64-thread blocks, candidate pairs (R8) ----
__global__ void __launch_bounds__(64, 6) k_knn64() {
    int b = blockIdx.y;
    int q = blockIdx.x * 64 + threadIdx.x;
    int gq = b*NN + q;

    ulonglong2 qr[16];                           // 64 dims as pairs
    const ulonglong2* qp = (const ulonglong2*)(g_xcur + gq*64);
    #pragma unroll
    for (int i = 0; i < 16; ++i) qr[i] = qp[i];
    float qn = g_norm[gq];

    float hd[KK]; int hi[KK];
    #pragma unroll
    for (int s = 0; s < KK; ++s) { hd[s] = 1e30f; hi[s] = 0; }

    __shared__ ulonglong2 sdb[64*16];            // 64 db points x 64 dims
    __shared__ float      sn[64];

    for (int jt = 0; jt < NN; jt += 64) {
        const ulonglong2* src = (const ulonglong2*)(g_xcur + (b*NN + jt)*64);
        #pragma unroll
        for (int u = 0; u < 16; ++u) sdb[threadIdx.x + u*64] = src[threadIdx.x + u*64];
        sn[threadIdx.x] = g_norm[b*NN + jt + threadIdx.x];
        __syncthreads();

        for (int jj = 0; jj < 64; jj += 2) {
            const ulonglong2* pa = sdb + jj*16;
            const ulonglong2* pb = pa + 16;
            ull a0=0ull,a1=0ull,a2=0ull,a3=0ull;
            ull c0=0ull,c1=0ull,c2=0ull,c3=0ull;
            #pragma unroll
            for (int i = 0; i < 16; i += 2) {
                ulonglong2 va0 = pa[i], va1 = pa[i+1];
                ulonglong2 vb0 = pb[i], vb1 = pb[i+1];
                ffma2(a0, va0.x, qr[i].x);   ffma2(a1, va0.y, qr[i].y);
                ffma2(a2, va1.x, qr[i+1].x); ffma2(a3, va1.y, qr[i+1].y);
                ffma2(c0, vb0.x, qr[i].x);   ffma2(c1, vb0.y, qr[i].y);
                ffma2(c2, vb1.x, qr[i+1].x); ffma2(c3, vb1.y, qr[i+1].y);
            }
            fadd2(a0, a1); fadd2(a2, a3); fadd2(a0, a2);
            fadd2(c0, c1); fadd2(c2, c3); fadd2(c0, c2);
            float la, ha, lc, hc;
            unpack2(la, ha, a0);
            unpack2(lc, hc, c0);
            float dA = qn + sn[jj]   - 2.f*(la + ha);
            float dB = qn + sn[jj+1] - 2.f*(lc + hc);

            int ja = jt + jj;
            if (ja != q && dA < hd[KK-1]) {
                float cd = dA; int ci = ja;
                #pragma unroll
                for (int s = 0; s < KK; ++s) {
                    if (cd < hd[s]) {
                        float td = hd[s]; int ti = hi[s];
                        hd[s] = cd; hi[s] = ci; cd = td; ci = ti;
                    }
                }
            }
            int jb = jt + jj + 1;
            if (jb != q && dB < hd[KK-1]) {
                float cd = dB; int ci = jb;
                #pragma unroll
                for (int s = 0; s < KK; ++s) {
                    if (cd < hd[s]) {
                        float td = hd[s]; int ti = hi[s];
                        hd[s] = cd; hi[s] = ci; cd = td; ci = ti;
                    }
                }
            }
        }
        __syncthreads();
    }
    #pragma unroll
    for (int s = 0; s < KK; ++s) g_idxf[gq*KK + s] = b*NN + hi[s];   // GLOBAL index
}

// ---------------- combos for ALL layers, once ----------------
__global__ void k_combo_all(const float* __restrict__ Wf1, const float* __restrict__ Wd1) {
    int i = blockIdx.x * 256 + threadIdx.x;     // 0..16383
    if (i < LL*4096) {
        int li = i >> 12, idx = i & 4095;
        const float* f = Wf1 + li*128*64;
        g_Cf1[i] = f[idx] - f[4096 + idx];
        const float* d = Wd1 + li*134*64;
        g_Cd1[i] = d[idx] - d[4096 + idx];
    }
}

// ---------------- per-point precompute: Af(+bf1), Bf, Ad(+bd1), Bd (f32x2, R8) --------
__global__ void k_pre(const float* __restrict__ coords,
                      const float* __restrict__ Wf1, const float* __restrict__ Wd1,
                      const float* __restrict__ bf1, const float* __restrict__ bd1, int li) {
    __shared__ float sX[32*65];
    __shared__ float sC[32*4];
    int tid = threadIdx.x;            // 256
    int p0 = blockIdx.x * 32;

    {
        int base = p0 * 64;
        #pragma unroll
        for (int u = 0; u < 8; ++u) {
            int f = tid + u*256;
            sX[(f >> 6)*65 + (f & 63)] = g_xcur[base + f];
        }
        if (tid < 96) { int pp = tid / 3, e = tid % 3; sC[pp*4 + e] = coords[(p0+pp)*3 + e]; }
    }
    __syncthreads();

    int w = tid >> 5, l = tid & 31;
    int c0 = w * 8;
    int p = p0 + l;

    const float* Cf  = g_Cf1 + li*4096;
    const float* Cd  = g_Cd1 + li*4096;
    const float* Wfb = Wf1 + li*128*64 + 64*64;     // rows 64..127
    const float* Wdb = Wd1 + li*134*64 + 64*64;     // rows 64..127
    const float* Wdc = Wd1 + li*134*64 + 128*64;    // rows 128..130 (ci)
    const float* Wdn = Wd1 + li*134*64 + 131*64;    // rows 131..133 (ncj)

    ull afp[4] = {0,0,0,0}, bfp[4] = {0,0,0,0};
    ull adp[4] = {0,0,0,0}, bdp[4] = {0,0,0,0};

    #pragma unroll 4
    for (int d = 0; d < 64; ++d) {
        float xv = sX[l*65 + d];
        ull xx = pack2(xv, xv);
        ulonglong2 a0 = __ldg((const ulonglong2*)(Cf + d*64 + c0));
        ulonglong2 a1 = __ldg((const ulonglong2*)(Cf + d*64 + c0 + 4));
        ulonglong2 b0 = __ldg((const ulonglong2*)(Wfb + d*64 + c0));
        ulonglong2 b1 = __ldg((const ulonglong2*)(Wfb + d*64 + c0 + 4));
        ulonglong2 e0 = __ldg((const ulonglong2*)(Cd + d*64 + c0));
        ulonglong2 e1 = __ldg((const ulonglong2*)(Cd + d*64 + c0 + 4));
        ulonglong2 f0 = __ldg((const ulonglong2*)(Wdb + d*64 + c0));
        ulonglong2 f1 = __ldg((const ulonglong2*)(Wdb + d*64 + c0 + 4));
        ffma2(afp[0], a0.x, xx); ffma2(afp[1], a0.y, xx);
        ffma2(afp[2], a1.x, xx); ffma2(afp[3], a1.y, xx);
        ffma2(bfp[0], b0.x, xx); ffma2(bfp[1], b0.y, xx);
        ffma2(bfp[2], b1.x, xx); ffma2(bfp[3], b1.y, xx);
        ffma2(adp[0], e0.x, xx); ffma2(adp[1], e0.y, xx);
        ffma2(adp[2], e1.x, xx); ffma2(adp[3], e1.y, xx);
        ffma2(bdp[0], f0.x, xx); ffma2(bdp[1], f0.y, xx);
        ffma2(bdp[2], f1.x, xx); ffma2(bdp[3], f1.y, xx);
    }
    #pragma unroll
    for (int e = 0; e < 3; ++e) {
        float cv = sC[l*4 + e];
        ull cc = pack2(cv, cv);
        ulonglong2 u0 = __ldg((const ulonglong2*)(Wdc + e*64 + c0));
        ulonglong2 u1 = __ldg((const ulonglong2*)(Wdc + e*64 + c0 + 4));
        ulonglong2 v0 = __ldg((const ulonglong2*)(Wdn + e*64 + c0));
        ulonglong2 v1 = __ldg((const ulonglong2*)(Wdn + e*64 + c0 + 4));
        ffma2(adp[0], u0.x, cc); ffma2(adp[1], u0.y, cc);
        ffma2(adp[2], u1.x, cc); ffma2(adp[3], u1.y, cc);
        ffma2(bdp[0], v0.x, cc); ffma2(bdp[1], v0.y, cc);
        ffma2(bdp[2], v1.x, cc); ffma2(bdp[3], v1.y, cc);
    }

    float af[8], bfv[8], ad[8], bdv[8];
    #pragma unroll
    for (int j = 0; j < 4; ++j) {
        unpack2(af[2*j],  af[2*j+1],  afp[j]);
        unpack2(bfv[2*j], bfv[2*j+1], bfp[j]);
        unpack2(ad[2*j],  ad[2*j+1],  adp[j]);
        unpack2(bdv[2*j], bdv[2*j+1], bdp[j]);
    }
    #pragma unroll
    for (int j = 0; j < 8; ++j) {
        af[j] += bf1[li*64 + c0 + j];   // fold bias into A (applied pre-leaky)
        ad[j] += bd1[li*64 + c0 + j];
    }
    int o = p*64 + c0;
    #pragma unroll
    for (int j = 0; j < 8; ++j) {
        g_Af[o+j] = af[j]; g_Bf[o+j] = bfv[j];
        g_Ad[o+j] = ad[j]; g_Bd[o+j] = bdv[j];
    }
}

// ---- fused edge kernel, both branches: blocks 0..1023 = f, 1024..2047 = d ----
__global__ void k_edge2(const float* __restrict__ Wf2g, const float* __restrict__ bf2,
                        const float* __restrict__ Wd2g, const float* __restrict__ bd2, int li) {
    int bid = blockIdx.x;
    int branch = bid >> 10;
    int p0 = (bid & 1023) * 32;

    const float* A    = branch ? g_Ad : g_Af;
    const float* Bm   = branch ? g_Bd : g_Bf;
    const int*   idx  = branch ? g_idxd : g_idxf;
    float*       Out  = branch ? g_Od : g_Of;
    const float* W    = (branch ? Wd2g : Wf2g) + li*64*64;
    const float* bias = (branch ? bd2 : bf2) + li*64;

    __shared__ float sA[32*65];
    __shared__ float sH[2][32*65];
    __shared__ __align__(16) float sW[64*64];
    __shared__ int sI[32*KK];

    int tid = threadIdx.x;            // 256

    #pragma unroll
    for (int u = 0; u < 16; ++u) sW[tid + u*256] = __ldg(W + tid + u*256);
    #pragma unroll
    for (int u = 0; u < 8; ++u) {
        int f = tid + u*256;
        sA[(f >> 6)*65 + (f & 63)] = A[p0*64 + f];
    }
    sI[tid]       = idx[p0*KK + tid];
    sI[tid + 256] = idx[p0*KK + tid + 256];
    __syncthreads();

    int w = tid >> 5, l = tid & 31;
    int c0 = w * 8;
    int pt = tid >> 3;                // 0..31: point for H staging
    int dd0 = (tid & 7) * 8;          // 8 dims of that point

    const ulonglong2* sW2 = (const ulonglong2*)sW;   // row d = 16 ulonglong2

    // prefetch B for k=0
    float4 v0, v1;
    {
        int j = sI[pt*KK];
        const float4* Brow = (const float4*)(Bm + j*64 + dd0);
        v0 = __ldg(Brow); v1 = __ldg(Brow + 1);
    }

    float best[8];
    #pragma unroll
    for (int j = 0; j < 8; ++j) best[j] = -1e30f;

    for (int k = 0; k < KK; ++k) {
        int buf = k & 1;
        float hb[8] = {v0.x, v0.y, v0.z, v0.w, v1.x, v1.y, v1.z, v1.w};
        #pragma unroll
        for (int u = 0; u < 8; ++u) {
            float h = sA[pt*65 + dd0 + u] + hb[u];
            sH[buf][pt*65 + dd0 + u] = h > 0.f ? h : 0.01f*h;
        }
        __syncthreads();

        if (k + 1 < KK) {
            int j = sI[pt*KK + k + 1];
            const float4* Brow = (const float4*)(Bm + j*64 + dd0);
            v0 = __ldg(Brow); v1 = __ldg(Brow + 1);
        }

        ull a0 = 0ull, a1 = 0ull, a2 = 0ull, a3 = 0ull;
        #pragma unroll
        for (int d = 0; d < 64; ++d) {
            float hv = sH[buf][l*65 + d];
            ull hh = pack2(hv, hv);
            ulonglong2 wa = sW2[d*16 + w*2];
            ulonglong2 wb = sW2[d*16 + w*2 + 1];
            ffma2(a0, wa.x, hh);
            ffma2(a1, wa.y, hh);
            ffma2(a2, wb.x, hh);
            ffma2(a3, wb.y, hh);
        }
        float t0,t1;
        unpack2(t0,t1,a0); best[0] = fmaxf(best[0], t0); best[1] = fmaxf(best[1], t1);
        unpack2(t0,t1,a1); best[2] = fmaxf(best[2], t0); best[3] = fmaxf(best[3], t1);
        unpack2(t0,t1,a2); best[4] = fmaxf(best[4], t0); best[5] = fmaxf(best[5], t1);
        unpack2(t0,t1,a3); best[6] = fmaxf(best[6], t0); best[7] = fmaxf(best[7], t1);
    }

    int p = p0 + l;
    #pragma unroll
    for (int j = 0; j < 8; ++j) Out[p*64 + c0 + j] = best[j] + bias[c0 + j];
}

// ---------------- combine branches, update xcur + xcat + norm ----------------
__global__ void k_combine(int li) {
    int t = blockIdx.x * 256 + threadIdx.x;     // float2 index, total BN*32
    float2 a = ((const float2*)g_Of)[t];
    float2 c = ((const float2*)g_Od)[t];
    float2 v; v.x = a.x + c.x; v.y = a.y + c.y;
    ((float2*)g_xcur)[t] = v;
    int p = t >> 5, pr = t & 31;
    ((float2*)(g_xcat + p*320))[pr + (li+1)*32] = v;
    float s = v.x*v.x + v.y*v.y;
    #pragma unroll
    for (int o = 16; o; o >>= 1) s += __shfl_down_sync(0xffffffffu, s, o);
    if ((threadIdx.x & 31) == 0) g_norm[p] = s;
}

// ---------------- site MLP: xcat[320] @ Ws[320,64] + bs (f32x2) ----------------
__global__ void k_site(const float* __restrict__ Ws, const float* __restrict__ bs) {
    __shared__ float sX[32*321];
    int tid = threadIdx.x;            // 256
    int p0 = blockIdx.x * 32;
    for (int u = 0; u < 40; ++u) {
        int f = tid + u*256;          // 0..10239
        sX[(f / 320)*321 + (f % 320)] = g_xcat[p0*320 + f];
    }
    __syncthreads();

    int w = tid >> 5, l = tid & 31;
    int c0 = w * 8;
    ull a0 = 0ull, a1 = 0ull, a2 = 0ull, a3 = 0ull;
    #pragma unroll 8
    for (int d = 0; d < 320; ++d) {
        float xv = sX[l*321 + d];
        ull xx = pack2(xv, xv);
        ulonglong2 w0 = __ldg((const ulonglong2*)(Ws + d*64 + c0));
        ulonglong2 w1 = __ldg((const ulonglong2*)(Ws + d*64 + c0 + 4));
        ffma2(a0, w0.x, xx);
        ffma2(a1, w0.y, xx);
        ffma2(a2, w1.x, xx);
        ffma2(a3, w1.y, xx);
    }
    float acc[8];
    unpack2(acc[0], acc[1], a0);
    unpack2(acc[2], acc[3], a1);
    unpack2(acc[4], acc[5], a2);
    unpack2(acc[6], acc[7], a3);
    int p = p0 + l;
    #pragma unroll
    for (int j = 0; j < 8; ++j) g_site[p*64 + c0 + j] = acc[j] + bs[c0 + j];
}

// ---------------- max pool over N ----------------
__global__ void k_pool() {
    int b = blockIdx.x;
    int tid = threadIdx.x;            // 256
    int c = tid & 63, g = tid >> 6;
    float m = -1e30f;
    for (int n = g; n < NN; n += 4) m = fmaxf(m, g_site[(b*NN + n)*64 + c]);
    __shared__ float red[256];
    red[tid] = m;
    __syncthreads();
    if (tid < 128) red[tid] = fmaxf(red[tid], red[tid + 128]);
    __syncthreads();
    if (tid < 64) g_pool[b*64 + tid] = fmaxf(red[tid], red[tid + 64]);
}

// ---------------- head ----------------
__global__ void k_head(const float* __restrict__ Wc1, const float* __restrict__ bc1,
                       const float* __restrict__ Wc2, const float* __restrict__ bc2,
                       float* __restrict__ out) {
    __shared__ float sp[BB*64], sh[BB*64];
    int tid = threadIdx.x;            // 512
    sp[tid] = g_pool[tid];
    __syncthreads();
    {
        int b = tid >> 6, c = tid & 63;
        float a = 0.f;
        #pragma unroll 8
        for (int d = 0; d < 64; ++d) a += sp[b*64 + d] * __ldg(Wc1 + d*64 + c);
        a += bc1[c];
        sh[tid] = a > 0.f ? a : 0.01f*a;
    }
    __syncthreads();
    if (tid < BB*3) {
        int b = tid / 3, e = tid % 3;
        float a = 0.f;
        #pragma unroll 8
        for (int c = 0; c < 64; ++c) a += sh[b*64 + c] * __ldg(Wc2 + c*3 + e);
        out[tid] = a + bc2[e];
    }
}

// ---------------- launcher ----------------
extern "C" void kernel_launch(void* const* d_in, const int* in_sizes, int n_in,
                              void* d_out, int out_size) {
    const float* feats  = (const float*)d_in[0];
    const float* coords = (const float*)d_in[1];
    const float* Wd1 = (const float*)d_in[2];
    const float* bd1 = (const float*)d_in[3];
    const float* Wd2 = (const float*)d_in[4];
    const float* bd2 = (const float*)d_in[5];
    const float* Wf1 = (const float*)d_in[6];
    const float* bf1 = (const float*)d_in[7];
    const float* Wf2 = (const float*)d_in[8];
    const float* bf2 = (const float*)d_in[9];
    const float* Ws  = (const float*)d_in[10];
    const float* bs  = (const float*)d_in[11];
    const float* Wc1 = (const float*)d_in[12];
    const float* bc1 = (const float*)d_in[13];
    const float* Wc2 = (const float*)d_in[14];
    const float* bc2 = (const float*)d_in[15];

    k_init<<<BN*32/256, 256>>>(feats);          // also writes g_norm for layer 0
    k_norm3<<<(BN + 255)/256, 256>>>(coords);
    {
        dim3 g(NN/128, BB);
        k_knn3<<<g, 128>>>(coords);
    }
    k_combo_all<<<(LL*4096 + 255)/256, 256>>>(Wf1, Wd1);
    for (int li = 0; li < LL; ++li) {
        {
            dim3 g(NN/64, BB);
            k_knn64<<<g, 64>>>();
        }
        k_pre<<<BN/32, 256>>>(coords, Wf1, Wd1, bf1, bd1, li);
        k_edge2<<<2*BN/32, 256>>>(Wf2, bf2, Wd2, bd2, li);
        k_combine<<<BN*32/256, 256>>>(li);      // also writes g_norm for next layer
    }
    k_site<<<BN/32, 256>>>(Ws, bs);
    k_pool<<<BB, 256>>>();
    k_head<<<1, 512>>>(Wc1, bc1, Wc2, bc2, (float*)d_out);
}

// round 16
// speedup vs baseline: 1.1831x; 1.0352x over previous
#include <cuda_runtime.h>

#define BB 8
#define NN 4096
#define DD 64
#define KK 16
#define LL 4
#define PREDN 64
#define BN (BB*NN)

typedef unsigned long long ull;

// ---- packed f32x2 helpers (sm_100a) ----
__device__ __forceinline__ void ffma2(ull& acc, ull a, ull b) {
    asm("fma.rn.f32x2 %0, %1, %2, %0;" : "+l"(acc) : "l"(a), "l"(b));
}
__device__ __forceinline__ void fadd2(ull& a, ull b) {
    asm("add.rn.f32x2 %0, %0, %1;" : "+l"(a) : "l"(b));
}
__device__ __forceinline__ ull pack2(float lo, float hi) {
    ull r; asm("mov.b64 %0, {%1, %2};" : "=l"(r) : "f"(lo), "f"(hi)); return r;
}
__device__ __forceinline__ void unpack2(float& lo, float& hi, ull v) {
    asm("mov.b64 {%0, %1}, %2;" : "=f"(lo), "=f"(hi) : "l"(v));
}

// ---------------- scratch (static device globals; no allocation) ----------------
__device__ float g_xcur[BN*DD];                 // current features
__device__ float g_xcat[BN*(LL+1)*DD];          // concat buffer [p][320]
__device__ float g_norm[BN];                    // |x|^2
__device__ float g_norm3[BN];                   // |c|^2
__device__ int   g_idxd[BN*KK];                 // coords knn (GLOBAL point indices)
__device__ int   g_idxf[BN*KK];                 // feature knn (GLOBAL point indices)
__device__ float g_Af[BN*DD], g_Bf[BN*DD], g_Ad[BN*DD], g_Bd[BN*DD];
__device__ float g_Of[BN*DD], g_Od[BN*DD];
__device__ float g_Cf1[LL*DD*DD], g_Cd1[LL*DD*DD];  // per-layer W1_top - W1_bot combos
__device__ float g_site[BN*PREDN];
__device__ float g_pool[BB*PREDN];

// ---------------- init: xcur = feats, xcat[:,0:64] = feats, norm ----------------
__global__ void k_init(const float* __restrict__ feats) {
    int t = blockIdx.x * 256 + threadIdx.x;     // float2 index, total BN*32
    float2 v = ((const float2*)feats)[t];
    ((float2*)g_xcur)[t] = v;
    int p = t >> 5, pr = t & 31;
    ((float2*)(g_xcat + p*320))[pr] = v;
    float s = v.x*v.x + v.y*v.y;
    #pragma unroll
    for (int o = 16; o; o >>= 1) s += __shfl_down_sync(0xffffffffu, s, o);
    if ((threadIdx.x & 31) == 0) g_norm[p] = s;
}

__global__ void k_norm3(const float* __restrict__ coords) {
    int p = blockIdx.x * 256 + threadIdx.x;
    if (p < BN) {
        float a = coords[p*3], b = coords[p*3+1], c = coords[p*3+2];
        g_norm3[p] = a*a + b*b + c*c;
    }
}

// ---------------- KNN on coords (D=3) ----------------
__global__ void k_knn3(const float* __restrict__ coords) {
    int b = blockIdx.y;
    int tid = threadIdx.x;                      // 128
    int q = blockIdx.x * 128 + tid;
    int gq = b*NN + q;
    float q0 = coords[gq*3+0], q1 = coords[gq*3+1], q2 = coords[gq*3+2];
    float qn = g_norm3[gq];
    float hd[KK]; int hi[KK];
    #pragma unroll
    for (int s = 0; s < KK; ++s) { hd[s] = 1e30f; hi[s] = 0; }

    __shared__ float s0[128], s1[128], s2[128], sn[128];
    for (int jt = 0; jt < NN; jt += 128) {
        int gj = b*NN + jt + tid;
        s0[tid] = coords[gj*3+0];
        s1[tid] = coords[gj*3+1];
        s2[tid] = coords[gj*3+2];
        sn[tid] = g_norm3[gj];
        __syncthreads();
        #pragma unroll 4
        for (int jj = 0; jj < 128; ++jj) {
            float d2 = qn + sn[jj] - 2.f*(q0*s0[jj] + q1*s1[jj] + q2*s2[jj]);
            int j = jt + jj;
            if (j != q && d2 < hd[KK-1]) {
                float cd = d2; int ci = j;
                #pragma unroll
                for (int s = 0; s < KK; ++s) {
                    if (cd < hd[s]) {
                        float td = hd[s]; int ti = hi[s];
                        hd[s] = cd; hi[s] = ci; cd = td; ci = ti;
                    }
                }
            }
        }
        __syncthreads();
    }
    #pragma unroll
    for (int s = 0; s < KK; ++s) g_idxd[gq*KK + s] = b*NN + hi[s];   // GLOBAL index
}

// ---- KNN on features (D=64): single pass, deferred-insert pending buffer ----
__global__ void __launch_bounds__(64, 6) k_knn64() {
    int b = blockIdx.y;
    int q = blockIdx.x * 64 + threadIdx.x;
    int gq = b*NN + q;

    ulonglong2 qr[16];                           // 64 dims as pairs
    const ulonglong2* qp = (const ulonglong2*)(g_xcur + gq*64);
    #pragma unroll
    for (int i = 0; i < 16; ++i) qr[i] = qp[i];
    float qn = g_norm[gq];

    float hd[KK]; int hi[KK];
    #pragma unroll
    for (int s = 0; s < KK; ++s) { hd[s] = 1e30f; hi[s] = 0; }

    // pending survivor FIFO: pd[0] newest, pd[2] oldest
    float pdq[3]; int piq[3]; int pc = 0;
    pdq[0] = pdq[1] = pdq[2] = 0.f; piq[0] = piq[1] = piq[2] = 0;

    __shared__ ulonglong2 sdb[64*16];            // 64 db points x 64 dims
    __shared__ float      sn[64];

    for (int jt = 0; jt < NN; jt += 64) {
        const ulonglong2* src = (const ulonglong2*)(g_xcur + (b*NN + jt)*64);
        #pragma unroll
        for (int u = 0; u < 16; ++u) sdb[threadIdx.x + u*64] = src[threadIdx.x + u*64];
        sn[threadIdx.x] = g_norm[b*NN + jt + threadIdx.x];
        __syncthreads();

        for (int jj = 0; jj < 64; jj += 2) {
            const ulonglong2* pa = sdb + jj*16;
            const ulonglong2* pb = pa + 16;
            ull a0=0ull,a1=0ull,a2=0ull,a3=0ull;
            ull c0=0ull,c1=0ull,c2=0ull,c3=0ull;
            #pragma unroll
            for (int i = 0; i < 16; i += 2) {
                ulonglong2 va0 = pa[i], va1 = pa[i+1];
                ulonglong2 vb0 = pb[i], vb1 = pb[i+1];
                ffma2(a0, va0.x, qr[i].x);   ffma2(a1, va0.y, qr[i].y);
                ffma2(a2, va1.x, qr[i+1].x); ffma2(a3, va1.y, qr[i+1].y);
                ffma2(c0, vb0.x, qr[i].x);   ffma2(c1, vb0.y, qr[i].y);
                ffma2(c2, vb1.x, qr[i+1].x); ffma2(c3, vb1.y, qr[i+1].y);
            }
            fadd2(a0, a1); fadd2(a2, a3); fadd2(a0, a2);
            fadd2(c0, c1); fadd2(c2, c3); fadd2(c0, c2);
            float la, ha, lc, hc;
            unpack2(la, ha, a0);
            unpack2(lc, hc, c0);
            float dA = qn + sn[jj]   - 2.f*(la + ha);
            float dB = qn + sn[jj+1] - 2.f*(lc + hc);

            int ja = jt + jj;
            int jb = jt + jj + 1;
            bool sA = (ja != q) && (dA < hd[KK-1]);
            bool sB = (jb != q) && (dB < hd[KK-1]);
            if (sA | sB) {
                if (sA) {
                    pdq[2]=pdq[1]; piq[2]=piq[1];
                    pdq[1]=pdq[0]; piq[1]=piq[0];
                    pdq[0]=dA; piq[0]=ja; ++pc;
                }
                if (sB) {
                    pdq[2]=pdq[1]; piq[2]=piq[1];
                    pdq[1]=pdq[0]; piq[1]=piq[0];
                    pdq[0]=dB; piq[0]=jb; ++pc;
                }
            }
            if (__any_sync(0xffffffffu, pc >= 2)) {
                // flush all pendings, oldest (smallest j) first
                #pragma unroll
                for (int u = 2; u >= 0; --u) {
                    if (pc > u) {
                        float cd = pdq[u]; int ci = piq[u];
                        #pragma unroll
                        for (int s = 0; s < KK; ++s) {
                            if (cd < hd[s]) {
                                float td = hd[s]; int ti = hi[s];
                                hd[s] = cd; hi[s] = ci; cd = td; ci = ti;
                            }
                        }
                    }
                }
                pc = 0;
            }
        }
        __syncthreads();
    }
    // final flush
    if (__any_sync(0xffffffffu, pc > 0)) {
        #pragma unroll
        for (int u = 2; u >= 0; --u) {
            if (pc > u) {
                float cd = pdq[u]; int ci = piq[u];
                #pragma unroll
                for (int s = 0; s < KK; ++s) {
                    if (cd < hd[s]) {
                        float td = hd[s]; int ti = hi[s];
                        hd[s] = cd; hi[s] = ci; cd = td; ci = ti;
                    }
                }
            }
        }
    }
    #pragma unroll
    for (int s = 0; s < KK; ++s) g_idxf[gq*KK + s] = b*NN + hi[s];   // GLOBAL index
}

// ---------------- combos for ALL layers, once ----------------
__global__ void k_combo_all(const float* __restrict__ Wf1, const float* __restrict__ Wd1) {
    int i = blockIdx.x * 256 + threadIdx.x;     // 0..16383
    if (i < LL*4096) {
        int li = i >> 12, idx = i & 4095;
        const float* f = Wf1 + li*128*64;
        g_Cf1[i] = f[idx] - f[4096 + idx];
        const float* d = Wd1 + li*134*64;
        g_Cd1[i] = d[idx] - d[4096 + idx];
    }
}

// ---------------- per-point precompute: Af(+bf1), Bf, Ad(+bd1), Bd (f32x2) --------
__global__ void k_pre(const float* __restrict__ coords,
                      const float* __restrict__ Wf1, const float* __restrict__ Wd1,
                      const float* __restrict__ bf1, const float* __restrict__ bd1, int li) {
    __shared__ float sX[32*65];
    __shared__ float sC[32*4];
    int tid = threadIdx.x;            // 256
    int p0 = blockIdx.x * 32;

    {
        int base = p0 * 64;
        #pragma unroll
        for (int u = 0; u < 8; ++u) {
            int f = tid + u*256;
            sX[(f >> 6)*65 + (f & 63)] = g_xcur[base + f];
        }
        if (tid < 96) { int pp = tid / 3, e = tid % 3; sC[pp*4 + e] = coords[(p0+pp)*3 + e]; }
    }
    __syncthreads();

    int w = tid >> 5, l = tid & 31;
    int c0 = w * 8;
    int p = p0 + l;

    const float* Cf  = g_Cf1 + li*4096;
    const float* Cd  = g_Cd1 + li*4096;
    const float* Wfb = Wf1 + li*128*64 + 64*64;     // rows 64..127
    const float* Wdb = Wd1 + li*134*64 + 64*64;     // rows 64..127
    const float* Wdc = Wd1 + li*134*64 + 128*64;    // rows 128..130 (ci)
    const float* Wdn = Wd1 + li*134*64 + 131*64;    // rows 131..133 (ncj)

    ull afp[4] = {0,0,0,0}, bfp[4] = {0,0,0,0};
    ull adp[4] = {0,0,0,0}, bdp[4] = {0,0,0,0};

    #pragma unroll 4
    for (int d = 0; d < 64; ++d) {
        float xv = sX[l*65 + d];
        ull xx = pack2(xv, xv);
        ulonglong2 a0 = __ldg((const ulonglong2*)(Cf + d*64 + c0));
        ulonglong2 a1 = __ldg((const ulonglong2*)(Cf + d*64 + c0 + 4));
        ulonglong2 b0 = __ldg((const ulonglong2*)(Wfb + d*64 + c0));
        ulonglong2 b1 = __ldg((const ulonglong2*)(Wfb + d*64 + c0 + 4));
        ulonglong2 e0 = __ldg((const ulonglong2*)(Cd + d*64 + c0));
        ulonglong2 e1 = __ldg((const ulonglong2*)(Cd + d*64 + c0 + 4));
        ulonglong2 f0 = __ldg((const ulonglong2*)(Wdb + d*64 + c0));
        ulonglong2 f1 = __ldg((const ulonglong2*)(Wdb + d*64 + c0 + 4));
        ffma2(afp[0], a0.x, xx); ffma2(afp[1], a0.y, xx);
        ffma2(afp[2], a1.x, xx); ffma2(afp[3], a1.y, xx);
        ffma2(bfp[0], b0.x, xx); ffma2(bfp[1], b0.y, xx);
        ffma2(bfp[2], b1.x, xx); ffma2(bfp[3], b1.y, xx);
        ffma2(adp[0], e0.x, xx); ffma2(adp[1], e0.y, xx);
        ffma2(adp[2], e1.x, xx); ffma2(adp[3], e1.y, xx);
        ffma2(bdp[0], f0.x, xx); ffma2(bdp[1], f0.y, xx);
        ffma2(bdp[2], f1.x, xx); ffma2(bdp[3], f1.y, xx);
    }
    #pragma unroll
    for (int e = 0; e < 3; ++e) {
        float cv = sC[l*4 + e];
        ull cc = pack2(cv, cv);
        ulonglong2 u0 = __ldg((const ulonglong2*)(Wdc + e*64 + c0));
        ulonglong2 u1 = __ldg((const ulonglong2*)(Wdc + e*64 + c0 + 4));
        ulonglong2 v0 = __ldg((const ulonglong2*)(Wdn + e*64 + c0));
        ulonglong2 v1 = __ldg((const ulonglong2*)(Wdn + e*64 + c0 + 4));
        ffma2(adp[0], u0.x, cc); ffma2(adp[1], u0.y, cc);
        ffma2(adp[2], u1.x, cc); ffma2(adp[3], u1.y, cc);
        ffma2(bdp[0], v0.x, cc); ffma2(bdp[1], v0.y, cc);
        ffma2(bdp[2], v1.x, cc); ffma2(bdp[3], v1.y, cc);
    }

    float af[8], bfv[8], ad[8], bdv[8];
    #pragma unroll
    for (int j = 0; j < 4; ++j) {
        unpack2(af[2*j],  af[2*j+1],  afp[j]);
        unpack2(bfv[2*j], bfv[2*j+1], bfp[j]);
        unpack2(ad[2*j],  ad[2*j+1],  adp[j]);
        unpack2(bdv[2*j], bdv[2*j+1], bdp[j]);
    }
    #pragma unroll
    for (int j = 0; j < 8; ++j) {
        af[j] += bf1[li*64 + c0 + j];   // fold bias into A (applied pre-leaky)
        ad[j] += bd1[li*64 + c0 + j];
    }
    int o = p*64 + c0;
    #pragma unroll
    for (int j = 0; j < 8; ++j) {
        g_Af[o+j] = af[j]; g_Bf[o+j] = bfv[j];
        g_Ad[o+j] = ad[j]; g_Bd[o+j] = bdv[j];
    }
}

// ---- fused edge kernel, both branches: blocks 0..1023 = f, 1024..2047 = d ----
__global__ void k_edge2(const float* __restrict__ Wf2g, const float* __restrict__ bf2,
                        const float* __restrict__ Wd2g, const float* __restrict__ bd2, int li) {
    int bid = blockIdx.x;
    int branch = bid >> 10;
    int p0 = (bid & 1023) * 32;

    const float* A    = branch ? g_Ad : g_Af;
    const float* Bm   = branch ? g_Bd : g_Bf;
    const int*   idx  = branch ? g_idxd : g_idxf;
    float*       Out  = branch ? g_Od : g_Of;
    const float* W    = (branch ? Wd2g : Wf2g) + li*64*64;
    const float* bias = (branch ? bd2 : bf2) + li*64;

    __shared__ float sA[32*65];
    __shared__ float sH[2][32*65];
    __shared__ __align__(16) float sW[64*64];
    __shared__ int sI[32*KK];

    int tid = threadIdx.x;            // 256

    #pragma unroll
    for (int u = 0; u < 16; ++u) sW[tid + u*256] = __ldg(W + tid + u*256);
    #pragma unroll
    for (int u = 0; u < 8; ++u) {
        int f = tid + u*256;
        sA[(f >> 6)*65 + (f & 63)] = A[p0*64 + f];
    }
    sI[tid]       = idx[p0*KK + tid];
    sI[tid + 256] = idx[p0*KK + tid + 256];
    __syncthreads();

    int w = tid >> 5, l = tid & 31;
    int c0 = w * 8;
    int pt = tid >> 3;                // 0..31: point for H staging
    int dd0 = (tid & 7) * 8;          // 8 dims of that point

    const ulonglong2* sW2 = (const ulonglong2*)sW;   // row d = 16 ulonglong2

    // prefetch B for k=0
    float4 v0, v1;
    {
        int j = sI[pt*KK];
        const float4* Brow = (const float4*)(Bm + j*64 + dd0);
        v0 = __ldg(Brow); v1 = __ldg(Brow + 1);
    }

    float best[8];
    #pragma unroll
    for (int j = 0; j < 8; ++j) best[j] = -1e30f;

    for (int k = 0; k < KK; ++k) {
        int buf = k & 1;
        float hb[8] = {v0.x, v0.y, v0.z, v0.w, v1.x, v1.y, v1.z, v1.w};
        #pragma unroll
        for (int u = 0; u < 8; ++u) {
            float h = sA[pt*65 + dd0 + u] + hb[u];
            sH[buf][pt*65 + dd0 + u] = h > 0.f ? h : 0.01f*h;
        }
        __syncthreads();

        if (k + 1 < KK) {
            int j = sI[pt*KK + k + 1];
            const float4* Brow = (const float4*)(Bm + j*64 + dd0);
            v0 = __ldg(Brow); v1 = __ldg(Brow + 1);
        }

        ull a0 = 0ull, a1 = 0ull, a2 = 0ull, a3 = 0ull;
        #pragma unroll
        for (int d = 0; d < 64; ++d) {
            float hv = sH[buf][l*65 + d];
            ull hh = pack2(hv, hv);
            ulonglong2 wa = sW2[d*16 + w*2];
            ulonglong2 wb = sW2[d*16 + w*2 + 1];
            ffma2(a0, wa.x, hh);
            ffma2(a1, wa.y, hh);
            ffma2(a2, wb.x, hh);
            ffma2(a3, wb.y, hh);
        }
        float t0,t1;
        unpack2(t0,t1,a0); best[0] = fmaxf(best[0], t0); best[1] = fmaxf(best[1], t1);
        unpack2(t0,t1,a1); best[2] = fmaxf(best[2], t0); best[3] = fmaxf(best[3], t1);
        unpack2(t0,t1,a2); best[4] = fmaxf(best[4], t0); best[5] = fmaxf(best[5], t1);
        unpack2(t0,t1,a3); best[6] = fmaxf(best[6], t0); best[7] = fmaxf(best[7], t1);
    }

    int p = p0 + l;
    #pragma unroll
    for (int j = 0; j < 8; ++j) Out[p*64 + c0 + j] = best[j] + bias[c0 + j];
}

// ---------------- combine branches, update xcur + xcat + norm ----------------
__global__ void k_combine(int li) {
    int t = blockIdx.x * 256 + threadIdx.x;     // float2 index, total BN*32
    float2 a = ((const float2*)g_Of)[t];
    float2 c = ((const float2*)g_Od)[t];
    float2 v; v.x = a.x + c.x; v.y = a.y + c.y;
    ((float2*)g_xcur)[t] = v;
    int p = t >> 5, pr = t & 31;
    ((float2*)(g_xcat + p*320))[pr + (li+1)*32] = v;
    float s = v.x*v.x + v.y*v.y;
    #pragma unroll
    for (int o = 16; o; o >>= 1) s += __shfl_down_sync(0xffffffffu, s, o);
    if ((threadIdx.x & 31) == 0) g_norm[p] = s;
}

// ---------------- site MLP: xcat[320] @ Ws[320,64] + bs (f32x2) ----------------
__global__ void k_site(const float* __restrict__ Ws, const float* __restrict__ bs) {
    __shared__ float sX[32*321];
    int tid = threadIdx.x;            // 256
    int p0 = blockIdx.x * 32;
    for (int u = 0; u < 40; ++u) {
        int f = tid + u*256;          // 0..10239
        sX[(f / 320)*321 + (f % 320)] = g_xcat[p0*320 + f];
    }
    __syncthreads();

    int w = tid >> 5, l = tid & 31;
    int c0 = w * 8;
    ull a0 = 0ull, a1 = 0ull, a2 = 0ull, a3 = 0ull;
    #pragma unroll 8
    for (int d = 0; d < 320; ++d) {
        float xv = sX[l*321 + d];
        ull xx = pack2(xv, xv);
        ulonglong2 w0 = __ldg((const ulonglong2*)(Ws + d*64 + c0));
        ulonglong2 w1 = __ldg((const ulonglong2*)(Ws + d*64 + c0 + 4));
        ffma2(a0, w0.x, xx);
        ffma2(a1, w0.y, xx);
        ffma2(a2, w1.x, xx);
        ffma2(a3, w1.y, xx);
    }
    float acc[8];
    unpack2(acc[0], acc[1], a0);
    unpack2(acc[2], acc[3], a1);
    unpack2(acc[4], acc[5], a2);
    unpack2(acc[6], acc[7], a3);
    int p = p0 + l;
    #pragma unroll
    for (int j = 0; j < 8; ++j) g_site[p*64 + c0 + j] = acc[j] + bs[c0 + j];
}

// ---------------- max pool over N ----------------
__global__ void k_pool() {
    int b = blockIdx.x;
    int tid = threadIdx.x;            // 256
    int c = tid & 63, g = tid >> 6;
    float m = -1e30f;
    for (int n = g; n < NN; n += 4) m = fmaxf(m, g_site[(b*NN + n)*64 + c]);
    __shared__ float red[256];
    red[tid] = m;
    __syncthreads();
    if (tid < 128) red[tid] = fmaxf(red[tid], red[tid + 128]);
    __syncthreads();
    if (tid < 64) g_pool[b*64 + tid] = fmaxf(red[tid], red[tid + 64]);
}

// ---------------- head ----------------
__global__ void k_head(const float* __restrict__ Wc1, const float* __restrict__ bc1,
                       const float* __restrict__ Wc2, const float* __restrict__ bc2,
                       float* __restrict__ out) {
    __shared__ float sp[BB*64], sh[BB*64];
    int tid = threadIdx.x;            // 512
    sp[tid] = g_pool[tid];
    __syncthreads();
    {
        int b = tid >> 6, c = tid & 63;
        float a = 0.f;
        #pragma unroll 8
        for (int d = 0; d < 64; ++d) a += sp[b*64 + d] * __ldg(Wc1 + d*64 + c);
        a += bc1[c];
        sh[tid] = a > 0.f ? a : 0.01f*a;
    }
    __syncthreads();
    if (tid < BB*3) {
        int b = tid / 3, e = tid % 3;
        float a = 0.f;
        #pragma unroll 8
        for (int c = 0; c < 64; ++c) a += sh[b*64 + c] * __ldg(Wc2 + c*3 + e);
        out[tid] = a + bc2[e];
    }
}

// ---------------- launcher ----------------
extern "C" void kernel_launch(void* const* d_in, const int* in_sizes, int n_in,
                              void* d_out, int out_size) {
    const float* feats  = (const float*)d_in[0];
    const float* coords = (const float*)d_in[1];
    const float* Wd1 = (const float*)d_in[2];
    const float* bd1 = (const float*)d_in[3];
    const float* Wd2 = (const float*)d_in[4];
    const float* bd2 = (const float*)d_in[5];
    const float* Wf1 = (const float*)d_in[6];
    const float* bf1 = (const float*)d_in[7];
    const float* Wf2 = (const float*)d_in[8];
    const float* bf2 = (const float*)d_in[9];
    const float* Ws  = (const float*)d_in[10];
    const float* bs  = (const float*)d_in[11];
    const float* Wc1 = (const float*)d_in[12];
    const float* bc1 = (const float*)d_in[13];
    const float* Wc2 = (const float*)d_in[14];
    const float* bc2 = (const float*)d_in[15];

    k_init<<<BN*32/256, 256>>>(feats);          // also writes g_norm for layer 0
    k_norm3<<<(BN + 255)/256, 256>>>(coords);
    {
        dim3 g(NN/128, BB);
        k_knn3<<<g, 128>>>(coords);
    }
    k_combo_all<<<(LL*4096 + 255)/256, 256>>>(Wf1, Wd1);
    for (int li = 0; li < LL; ++li) {
        {
            dim3 g(NN/64, BB);
            k_knn64<<<g, 64>>>();
        }
        k_pre<<<BN/32, 256>>>(coords, Wf1, Wd1, bf1, bd1, li);
        k_edge2<<<2*BN/32, 256>>>(Wf2, bf2, Wd2, bd2, li);
        k_combine<<<BN*32/256, 256>>>(li);      // also writes g_norm for next layer
    }
    k_site<<<BN/32, 256>>>(Ws, bs);
    k_pool<<<BB, 256>>>();
    k_head<<<1, 512>>>(Wc1, bc1, Wc2, bc2, (float*)d_out);
}